// round 1
// baseline (speedup 1.0000x reference)
#include <cuda_runtime.h>
#include <cuda_bf16.h>
#include <math.h>

// ---------------- problem constants ----------------
#define VOCAB   10000
#define D_GNN   64
#define L_TOK   8
#define DG      256
#define NH      4
#define HD      64          // DG/NH
#define N_NODES 8192
#define N_EDGES 2048
#define FD      512         // L_TOK * D_GNN
#define ROWS    16384       // N_EDGES * L_TOK

// ---------------- scratch (static device memory; no allocations) ----------------
__device__ float g_x   [N_NODES * FD];       // node embeddings [8192,512]
__device__ float g_e   [N_EDGES * FD];       // edge embeddings [2048,512]
__device__ float g_msg [N_EDGES * FD];
__device__ float g_agg [N_NODES * FD];
__device__ float g_h   [N_NODES * FD];
__device__ float g_eh  [N_EDGES * FD];       // == z [16384,64]
__device__ float g_zg  [ROWS * DG];          // after lc1  [16384,256]
__device__ float g_q   [ROWS * DG];
__device__ float g_k   [ROWS * DG];
__device__ float g_v   [ROWS * DG];
__device__ float g_ao  [ROWS * DG];          // attention output (pre-Wo)
__device__ float g_x1  [ROWS * DG];
__device__ float g_ffn [ROWS * 4 * DG];      // [16384,1024]
__device__ float g_x2  [ROWS * DG];
__device__ float g_y   [ROWS * D_GNN];       // [16384,64]
__device__ float g_embT[D_GNN * VOCAB];      // emb transposed [64,10000]
__device__ int   g_mtok[N_EDGES * L_TOK];
__device__ float g_rmax[ROWS];
__device__ float g_rinv[ROWS];
__device__ int   g_mask_mode;                // 0=int32, 1=float32, 2=uint8

// ---------------- mask dtype detection ----------------
// Read first 512 int32 words (== 2048 bytes: safe under int32/f32/uint8 layouts).
__global__ void detect_mask_kernel(const int* __restrict__ mr) {
    __shared__ int notint, notflt;
    if (threadIdx.x == 0) { notint = 0; notflt = 0; }
    __syncthreads();
    int w = mr[threadIdx.x];
    if (w != 0 && w != 1)          atomicExch(&notint, 1);
    if (w != 0 && w != 0x3F800000) atomicExch(&notflt, 1);
    __syncthreads();
    if (threadIdx.x == 0)
        g_mask_mode = notint ? (notflt ? 2 : 1) : 0;
}

// ---------------- labels + masked tokens ----------------
__global__ void mask_kernel(const int* __restrict__ etok, const void* __restrict__ maskraw,
                            float* labels_out /* nullable */) {
    int i = blockIdx.x * blockDim.x + threadIdx.x;
    if (i >= N_EDGES * L_TOK) return;
    int e = i >> 3;          // /L_TOK
    int t = etok[i];
    bool mr;
    int mode = g_mask_mode;
    if (mode == 0)      mr = ((const int*)maskraw)[e] != 0;
    else if (mode == 1) mr = ((const float*)maskraw)[e] != 0.0f;
    else                mr = ((const unsigned char*)maskraw)[e] != 0;
    bool msk = mr && (t >= 4);          // special tokens are {0,1,2,3}
    g_mtok[i] = msk ? 4 : t;            // MASK_ID = 4
    if (labels_out) labels_out[i] = msk ? (float)t : -100.0f;
}

// ---------------- embedding gathers ----------------
__global__ void embed_kernel(const int* __restrict__ tok, const float* __restrict__ emb,
                             float* __restrict__ out, int total) {
    int i = blockIdx.x * blockDim.x + threadIdx.x;
    if (i >= total) return;
    int ti = i >> 6;        // /64
    int d  = i & 63;
    out[i] = emb[tok[ti] * 64 + d];
}

__global__ void transpose_emb_kernel(const float* __restrict__ emb) {
    int i = blockIdx.x * blockDim.x + threadIdx.x;
    if (i >= D_GNN * VOCAB) return;
    int k = i / VOCAB, v = i - k * VOCAB;
    g_embT[i] = emb[v * 64 + k];
}

// ---------------- misc elementwise ----------------
__global__ void zero_kernel(float* __restrict__ p, int n) {
    int i = blockIdx.x * blockDim.x + threadIdx.x;
    if (i < n) p[i] = 0.0f;
}

__global__ void scatter_add_kernel(const int* __restrict__ dst) {
    int i = blockIdx.x * blockDim.x + threadIdx.x;
    if (i >= N_EDGES * FD) return;
    int e = i >> 9, c = i & 511;
    atomicAdd(&g_agg[dst[e] * FD + c], g_msg[i]);
}

__global__ void edge_gather_kernel(const int* __restrict__ src, const int* __restrict__ dst) {
    int i = blockIdx.x * blockDim.x + threadIdx.x;
    if (i >= N_EDGES * FD) return;
    int e = i >> 9, c = i & 511;
    g_eh[i] = g_h[src[e] * FD + c] + g_h[dst[e] * FD + c];
}

// ---------------- generic tiled SGEMM with fused epilogues ----------------
// C[M,N] = epi(A[M,K] @ B[K,N])
// EPI: 0 plain | 1 +bias[n] | 2 relu(+extra[m*ld+n]) | 3 relu(+extra[gidx[m]*ld+n])
//      4 +extra[m*ld+n] | 5 gelu
#define BM 128
#define BN 128
#define BK 16

template<int EPI>
__global__ void __launch_bounds__(256)
sgemm_k(const float* __restrict__ A, const float* __restrict__ B, float* __restrict__ C,
        int M, int N, int K,
        const float* __restrict__ extra, const int* __restrict__ gidx, int ldex) {
    __shared__ float As[BK][BM];
    __shared__ float Bs[BK][BN];
    int tid = threadIdx.x;
    int tx = tid & 15, ty = tid >> 4;
    int m0 = blockIdx.y * BM;
    int n0 = blockIdx.x * BN;
    float acc[8][8] = {};

    for (int k0 = 0; k0 < K; k0 += BK) {
        #pragma unroll
        for (int i = 0; i < 8; i++) {
            int t = tid + i * 256;
            int m = t >> 4, k = t & 15;
            As[k][m] = A[(size_t)(m0 + m) * K + k0 + k];
        }
        #pragma unroll
        for (int i = 0; i < 8; i++) {
            int t = tid + i * 256;
            int k = t >> 7, n = t & 127;
            int gn = n0 + n;
            Bs[k][n] = (gn < N) ? B[(size_t)(k0 + k) * N + gn] : 0.0f;
        }
        __syncthreads();
        #pragma unroll
        for (int kk = 0; kk < BK; kk++) {
            float a[8], b[8];
            #pragma unroll
            for (int i = 0; i < 8; i++) a[i] = As[kk][ty * 8 + i];
            #pragma unroll
            for (int j = 0; j < 8; j++) b[j] = Bs[kk][tx * 8 + j];
            #pragma unroll
            for (int i = 0; i < 8; i++)
                #pragma unroll
                for (int j = 0; j < 8; j++)
                    acc[i][j] += a[i] * b[j];
        }
        __syncthreads();
    }

    #pragma unroll
    for (int i = 0; i < 8; i++) {
        int m = m0 + ty * 8 + i;
        int ebase = 0;
        if (EPI == 2 || EPI == 4) ebase = m * ldex;
        if (EPI == 3)             ebase = gidx[m] * ldex;
        #pragma unroll
        for (int j = 0; j < 8; j++) {
            int n = n0 + tx * 8 + j;
            if (n < N) {
                float c = acc[i][j];
                if (EPI == 1) c += extra[n];
                else if (EPI == 2 || EPI == 3) c = fmaxf(c + extra[ebase + n], 0.0f);
                else if (EPI == 4) c += extra[ebase + n];
                else if (EPI == 5) {
                    float x = c;
                    c = 0.5f * x * (1.0f + tanhf(0.7978845608028654f * (x + 0.044715f * x * x * x)));
                }
                C[(size_t)m * N + n] = c;
            }
        }
    }
}

// ---------------- attention (B=2048 edges, S=8, NH=4, HD=64) ----------------
__global__ void __launch_bounds__(256) attention_kernel() {
    __shared__ float qs[8][DG], ks[8][DG], vs[8][DG];
    int b = blockIdx.x;
    int tid = threadIdx.x;
    for (int i = tid; i < 8 * DG; i += 256) {
        int s = i >> 8, c = i & 255;
        size_t off = (size_t)(b * 8 + s) * DG + c;
        qs[s][c] = g_q[off];
        ks[s][c] = g_k[off];
        vs[s][c] = g_v[off];
    }
    __syncthreads();

    int h  = tid >> 6;
    int qx = (tid >> 3) & 7;
    int kx = tid & 7;
    float att = 0.0f;
    #pragma unroll
    for (int d = 0; d < HD; d++)
        att += qs[qx][h * HD + d] * ks[kx][h * HD + d];
    att *= 0.125f;   // 1/sqrt(64)

    // softmax over kx within 8-lane group (groups are 8-aligned within warps)
    float mx = att;
    mx = fmaxf(mx, __shfl_xor_sync(0xffffffffu, mx, 4));
    mx = fmaxf(mx, __shfl_xor_sync(0xffffffffu, mx, 2));
    mx = fmaxf(mx, __shfl_xor_sync(0xffffffffu, mx, 1));
    float ex = expf(att - mx);
    float sm = ex;
    sm += __shfl_xor_sync(0xffffffffu, sm, 4);
    sm += __shfl_xor_sync(0xffffffffu, sm, 2);
    sm += __shfl_xor_sync(0xffffffffu, sm, 1);
    float a = ex / sm;

    int lane = tid & 31;
    int base = lane & ~7;
    float a_all[8];
    #pragma unroll
    for (int kk = 0; kk < 8; kk++)
        a_all[kk] = __shfl_sync(0xffffffffu, a, base + kk);

    // thread kx writes output dims [kx*8, kx*8+8) for (h, qx)
    #pragma unroll
    for (int t2 = 0; t2 < 8; t2++) {
        int d = kx * 8 + t2;
        float o = 0.0f;
        #pragma unroll
        for (int kk = 0; kk < 8; kk++)
            o += a_all[kk] * vs[kk][h * HD + d];
        g_ao[(size_t)(b * 8 + qx) * DG + h * HD + d] = o;
    }
}

// ---------------- LM-head softmax ----------------
__global__ void row_softmax_stats(const float* __restrict__ logits) {
    int row = blockIdx.x;
    const float* p = logits + (size_t)row * VOCAB;
    __shared__ float sm[256];
    float m = -1e30f;
    for (int i = threadIdx.x; i < VOCAB; i += 256) m = fmaxf(m, p[i]);
    sm[threadIdx.x] = m; __syncthreads();
    for (int s = 128; s > 0; s >>= 1) {
        if (threadIdx.x < s) sm[threadIdx.x] = fmaxf(sm[threadIdx.x], sm[threadIdx.x + s]);
        __syncthreads();
    }
    float M = sm[0]; __syncthreads();
    float ssum = 0.0f;
    for (int i = threadIdx.x; i < VOCAB; i += 256) ssum += expf(p[i] - M);
    sm[threadIdx.x] = ssum; __syncthreads();
    for (int s = 128; s > 0; s >>= 1) {
        if (threadIdx.x < s) sm[threadIdx.x] += sm[threadIdx.x + s];
        __syncthreads();
    }
    if (threadIdx.x == 0) { g_rmax[row] = M; g_rinv[row] = 1.0f / sm[0]; }
}

__global__ void softmax_normalize(float* __restrict__ probs) {
    int col = blockIdx.x * 256 + threadIdx.x;
    int row = blockIdx.y;
    if (col >= VOCAB) return;
    size_t idx = (size_t)row * VOCAB + col;
    probs[idx] = expf(probs[idx] - g_rmax[row]) * g_rinv[row];
}

// ---------------- host launcher ----------------
static void launch_gemm(int epi, const float* A, const float* B, float* C,
                        int M, int N, int K,
                        const float* extra = nullptr, const int* gidx = nullptr, int ldex = 0) {
    dim3 grid((N + BN - 1) / BN, M / BM), blk(256);
    switch (epi) {
        case 0: sgemm_k<0><<<grid, blk>>>(A, B, C, M, N, K, extra, gidx, ldex); break;
        case 1: sgemm_k<1><<<grid, blk>>>(A, B, C, M, N, K, extra, gidx, ldex); break;
        case 2: sgemm_k<2><<<grid, blk>>>(A, B, C, M, N, K, extra, gidx, ldex); break;
        case 3: sgemm_k<3><<<grid, blk>>>(A, B, C, M, N, K, extra, gidx, ldex); break;
        case 4: sgemm_k<4><<<grid, blk>>>(A, B, C, M, N, K, extra, gidx, ldex); break;
        case 5: sgemm_k<5><<<grid, blk>>>(A, B, C, M, N, K, extra, gidx, ldex); break;
    }
}

template <typename T>
static T* sym_addr(const void* sym) {
    void* p = nullptr;
    cudaGetSymbolAddress(&p, sym);
    return (T*)p;
}

extern "C" void kernel_launch(void* const* d_in, const int* in_sizes, int n_in,
                              void* d_out, int out_size) {
    const int*   node_tokens = (const int*)d_in[0];
    const int*   edge_tokens = (const int*)d_in[1];
    const int*   edge_index  = (const int*)d_in[2];
    const void*  mask_rows   = d_in[3];
    const float* emb    = (const float*)d_in[4];
    const float* W_msg  = (const float*)d_in[5];
    const float* W_node = (const float*)d_in[6];
    const float* lc1_w  = (const float*)d_in[7];
    const float* lc1_b  = (const float*)d_in[8];
    const float* lc2_w  = (const float*)d_in[9];
    const float* lc2_b  = (const float*)d_in[10];
    const float* Wq  = (const float*)d_in[11];
    const float* Wk  = (const float*)d_in[12];
    const float* Wv  = (const float*)d_in[13];
    const float* Wo  = (const float*)d_in[14];
    const float* Wf1 = (const float*)d_in[15];
    const float* Wf2 = (const float*)d_in[16];

    float* out = (float*)d_out;
    bool concat = (out_size != ROWS * VOCAB);  // default: [labels; probs] concatenated
    float* labels_out = concat ? out : nullptr;
    float* probs      = concat ? out + ROWS : out;

    const int* src = edge_index;            // edge_index[0]
    const int* dst = edge_index + N_EDGES;  // edge_index[1]

    float* px   = sym_addr<float>(g_x);
    float* pe   = sym_addr<float>(g_e);
    float* pmsg = sym_addr<float>(g_msg);
    float* pagg = sym_addr<float>(g_agg);
    float* ph   = sym_addr<float>(g_h);
    float* peh  = sym_addr<float>(g_eh);
    float* pzg  = sym_addr<float>(g_zg);
    float* pq   = sym_addr<float>(g_q);
    float* pk   = sym_addr<float>(g_k);
    float* pv   = sym_addr<float>(g_v);
    float* pao  = sym_addr<float>(g_ao);
    float* px1  = sym_addr<float>(g_x1);
    float* pffn = sym_addr<float>(g_ffn);
    float* px2  = sym_addr<float>(g_x2);
    float* py   = sym_addr<float>(g_y);
    float* pembT= sym_addr<float>(g_embT);
    int*   pmt  = sym_addr<int>(g_mtok);

    // 1. mask dtype detect + labels/masked tokens
    detect_mask_kernel<<<1, 512>>>((const int*)mask_rows);
    mask_kernel<<<(N_EDGES * L_TOK + 255) / 256, 256>>>(edge_tokens, mask_rows, labels_out);

    // 2. embeddings
    embed_kernel<<<(N_NODES * FD + 255) / 256, 256>>>(node_tokens, emb, px, N_NODES * FD);
    embed_kernel<<<(N_EDGES * FD + 255) / 256, 256>>>(pmt, emb, pe, N_EDGES * FD);
    transpose_emb_kernel<<<(D_GNN * VOCAB + 255) / 256, 256>>>(emb);

    // 3. GNN
    launch_gemm(3, pe, W_msg, pmsg, N_EDGES, FD, FD, px, src, FD);       // msg = relu(e@W_msg + x[src])
    zero_kernel<<<(N_NODES * FD + 255) / 256, 256>>>(pagg, N_NODES * FD);
    scatter_add_kernel<<<(N_EDGES * FD + 255) / 256, 256>>>(dst);
    launch_gemm(2, px, W_node, ph, N_NODES, FD, FD, pagg, nullptr, FD);  // h = relu(x@W_node + agg)
    edge_gather_kernel<<<(N_EDGES * FD + 255) / 256, 256>>>(src, dst);   // eh = h[src]+h[dst]

    // 4. lc1: [16384,64] @ [64,256] + b
    launch_gemm(1, peh, lc1_w, pzg, ROWS, DG, D_GNN, lc1_b);

    // 5. transformer
    launch_gemm(0, pzg, Wq, pq, ROWS, DG, DG);
    launch_gemm(0, pzg, Wk, pk, ROWS, DG, DG);
    launch_gemm(0, pzg, Wv, pv, ROWS, DG, DG);
    attention_kernel<<<N_EDGES, 256>>>();
    launch_gemm(4, pao, Wo, px1, ROWS, DG, DG, pzg, nullptr, DG);        // x1 = zg + ao@Wo
    launch_gemm(5, px1, Wf1, pffn, ROWS, 4 * DG, DG);                    // gelu(x1@Wf1)
    launch_gemm(4, pffn, Wf2, px2, ROWS, DG, 4 * DG, px1, nullptr, DG);  // x2 = x1 + ffn@Wf2

    // 6. lc2 + LM head + softmax
    launch_gemm(1, px2, lc2_w, py, ROWS, D_GNN, DG, lc2_b);
    launch_gemm(0, py, pembT, probs, ROWS, VOCAB, D_GNN);                // logits into out region
    row_softmax_stats<<<ROWS, 256>>>(probs);
    dim3 ngrid((VOCAB + 255) / 256, ROWS);
    softmax_normalize<<<ngrid, 256>>>(probs);
}

// round 2
// speedup vs baseline: 1.7947x; 1.7947x over previous
#include <cuda_runtime.h>
#include <cuda_bf16.h>
#include <math.h>
#include <stdint.h>

// ---------------- problem constants ----------------
#define VOCAB   10000
#define D_GNN   64
#define L_TOK   8
#define DG      256
#define NH      4
#define HD      64          // DG/NH
#define N_NODES 8192
#define N_EDGES 2048
#define FD      512         // L_TOK * D_GNN
#define ROWS    16384       // N_EDGES * L_TOK

// ---------------- scratch (static device memory; no allocations) ----------------
__device__ float g_x   [N_NODES * FD];
__device__ float g_e   [N_EDGES * FD];
__device__ float g_msg [N_EDGES * FD];
__device__ float g_agg [N_NODES * FD];
__device__ float g_h   [N_NODES * FD];
__device__ float g_eh  [N_EDGES * FD];
__device__ float g_zg  [ROWS * DG];
__device__ float g_q   [ROWS * DG];
__device__ float g_k   [ROWS * DG];
__device__ float g_v   [ROWS * DG];
__device__ float g_ao  [ROWS * DG];
__device__ float g_x1  [ROWS * DG];
__device__ float g_ffn [ROWS * 4 * DG];
__device__ float g_x2  [ROWS * DG];
__device__ float g_y   [ROWS * D_GNN];
__device__ float g_embT[D_GNN * VOCAB];
__device__ int   g_mtok[N_EDGES * L_TOK];
__device__ float g_rmax[ROWS];
__device__ float g_rinv[ROWS];
__device__ int   g_mask_mode;

// ---------------- mask dtype detection ----------------
__global__ void detect_mask_kernel(const int* __restrict__ mr) {
    __shared__ int notint, notflt;
    if (threadIdx.x == 0) { notint = 0; notflt = 0; }
    __syncthreads();
    int w = mr[threadIdx.x];
    if (w != 0 && w != 1)          atomicExch(&notint, 1);
    if (w != 0 && w != 0x3F800000) atomicExch(&notflt, 1);
    __syncthreads();
    if (threadIdx.x == 0)
        g_mask_mode = notint ? (notflt ? 2 : 1) : 0;
}

__global__ void mask_kernel(const int* __restrict__ etok, const void* __restrict__ maskraw,
                            float* labels_out) {
    int i = blockIdx.x * blockDim.x + threadIdx.x;
    if (i >= N_EDGES * L_TOK) return;
    int e = i >> 3;
    int t = etok[i];
    bool mr;
    int mode = g_mask_mode;
    if (mode == 0)      mr = ((const int*)maskraw)[e] != 0;
    else if (mode == 1) mr = ((const float*)maskraw)[e] != 0.0f;
    else                mr = ((const unsigned char*)maskraw)[e] != 0;
    bool msk = mr && (t >= 4);
    g_mtok[i] = msk ? 4 : t;
    if (labels_out) labels_out[i] = msk ? (float)t : -100.0f;
}

__global__ void embed_kernel(const int* __restrict__ tok, const float* __restrict__ emb,
                             float* __restrict__ out, int total) {
    int i = blockIdx.x * blockDim.x + threadIdx.x;
    if (i >= total) return;
    int ti = i >> 6;
    int d  = i & 63;
    out[i] = emb[tok[ti] * 64 + d];
}

__global__ void transpose_emb_kernel(const float* __restrict__ emb) {
    int i = blockIdx.x * blockDim.x + threadIdx.x;
    if (i >= D_GNN * VOCAB) return;
    int k = i / VOCAB, v = i - k * VOCAB;
    g_embT[i] = emb[v * 64 + k];
}

__global__ void zero_kernel(float* __restrict__ p, int n) {
    int i = blockIdx.x * blockDim.x + threadIdx.x;
    if (i < n) p[i] = 0.0f;
}

__global__ void scatter_add_kernel(const int* __restrict__ dst) {
    int i = blockIdx.x * blockDim.x + threadIdx.x;
    if (i >= N_EDGES * FD) return;
    int e = i >> 9, c = i & 511;
    atomicAdd(&g_agg[dst[e] * FD + c], g_msg[i]);
}

__global__ void edge_gather_kernel(const int* __restrict__ src, const int* __restrict__ dst) {
    int i = blockIdx.x * blockDim.x + threadIdx.x;
    if (i >= N_EDGES * FD) return;
    int e = i >> 9, c = i & 511;
    g_eh[i] = g_h[src[e] * FD + c] + g_h[dst[e] * FD + c];
}

// ---------------- tf32 tensor-core GEMM ----------------
// C[M,N] = epi(A[M,K] @ B[K,N]); M % 128 == 0, K % 16 == 0, N arbitrary.
// EPI: 0 plain | 1 +bias[n] | 2 relu(+extra[m*ld+n]) | 3 relu(+extra[gidx[m]*ld+n])
//      4 +extra[m*ld+n] | 5 gelu

__device__ __forceinline__ float to_tf32(float x) {
    asm("cvt.rna.tf32.f32 %0, %0;" : "+f"(x));
    return x;
}

__device__ __forceinline__ void mma_tf32(float c[4], const uint32_t a[4], const uint32_t b[2]) {
    asm volatile(
        "mma.sync.aligned.m16n8k8.row.col.f32.tf32.tf32.f32 "
        "{%0,%1,%2,%3}, {%4,%5,%6,%7}, {%8,%9}, {%0,%1,%2,%3};"
        : "+f"(c[0]), "+f"(c[1]), "+f"(c[2]), "+f"(c[3])
        : "r"(a[0]), "r"(a[1]), "r"(a[2]), "r"(a[3]), "r"(b[0]), "r"(b[1]));
}

#define TBM 128
#define TBN 128
#define TBK 16
#define SSTR 136   // smem row stride (floats): bank = tig*8+g -> all distinct

template<int EPI>
__global__ void __launch_bounds__(256)
tmma_k(const float* __restrict__ A, const float* __restrict__ B, float* __restrict__ C,
       int M, int N, int K,
       const float* __restrict__ extra, const int* __restrict__ gidx, int ldex) {
    __shared__ float As[TBK][SSTR];
    __shared__ float Bs[TBK][SSTR];
    int tid  = threadIdx.x;
    int lane = tid & 31;
    int warp = tid >> 5;
    int wm = warp & 1;        // 0..1 -> 64 rows each
    int wn = warp >> 1;       // 0..3 -> 32 cols each
    int g   = lane >> 2;
    int tig = lane & 3;
    int m0 = blockIdx.y * TBM;
    int n0 = blockIdx.x * TBN;

    float acc[4][4][4] = {};

    for (int k0 = 0; k0 < K; k0 += TBK) {
        // load A tile: As[k][m] (transposed, tf32-rounded)
        #pragma unroll
        for (int i = 0; i < 2; i++) {
            int slot = tid + i * 256;          // 512 slots = 128 m x 4 k-quads
            int m = slot >> 2;
            int q = (slot & 3) << 2;
            float4 v = *(const float4*)(A + (size_t)(m0 + m) * K + k0 + q);
            As[q + 0][m] = to_tf32(v.x);
            As[q + 1][m] = to_tf32(v.y);
            As[q + 2][m] = to_tf32(v.z);
            As[q + 3][m] = to_tf32(v.w);
        }
        // load B tile: Bs[k][n]
        #pragma unroll
        for (int i = 0; i < 2; i++) {
            int slot = tid + i * 256;          // 512 slots = 16 k x 32 n-quads
            int k  = slot >> 5;
            int n4 = (slot & 31) << 2;
            int gn = n0 + n4;
            float4 v;
            if (gn + 3 < N) {
                v = *(const float4*)(B + (size_t)(k0 + k) * N + gn);
            } else {
                const float* bp = B + (size_t)(k0 + k) * N;
                v.x = (gn + 0 < N) ? bp[gn + 0] : 0.0f;
                v.y = (gn + 1 < N) ? bp[gn + 1] : 0.0f;
                v.z = (gn + 2 < N) ? bp[gn + 2] : 0.0f;
                v.w = (gn + 3 < N) ? bp[gn + 3] : 0.0f;
            }
            v.x = to_tf32(v.x); v.y = to_tf32(v.y);
            v.z = to_tf32(v.z); v.w = to_tf32(v.w);
            *(float4*)&Bs[k][n4] = v;
        }
        __syncthreads();

        #pragma unroll
        for (int ks = 0; ks < TBK; ks += 8) {
            uint32_t af[4][4], bf[4][2];
            #pragma unroll
            for (int mt = 0; mt < 4; mt++) {
                int rm = wm * 64 + mt * 16 + g;
                af[mt][0] = __float_as_uint(As[ks + tig    ][rm    ]);
                af[mt][1] = __float_as_uint(As[ks + tig    ][rm + 8]);
                af[mt][2] = __float_as_uint(As[ks + tig + 4][rm    ]);
                af[mt][3] = __float_as_uint(As[ks + tig + 4][rm + 8]);
            }
            #pragma unroll
            for (int nt = 0; nt < 4; nt++) {
                int cn = wn * 32 + nt * 8 + g;
                bf[nt][0] = __float_as_uint(Bs[ks + tig    ][cn]);
                bf[nt][1] = __float_as_uint(Bs[ks + tig + 4][cn]);
            }
            #pragma unroll
            for (int mt = 0; mt < 4; mt++)
                #pragma unroll
                for (int nt = 0; nt < 4; nt++)
                    mma_tf32(acc[mt][nt], af[mt], bf[nt]);
        }
        __syncthreads();
    }

    // epilogue
    #pragma unroll
    for (int mt = 0; mt < 4; mt++) {
        int r0 = m0 + wm * 64 + mt * 16 + g;
        #pragma unroll
        for (int half = 0; half < 2; half++) {
            int r = r0 + half * 8;
            int ebase = 0;
            if (EPI == 2 || EPI == 4) ebase = r * ldex;
            if (EPI == 3)             ebase = gidx[r] * ldex;
            #pragma unroll
            for (int nt = 0; nt < 4; nt++) {
                #pragma unroll
                for (int jj = 0; jj < 2; jj++) {
                    int n = n0 + wn * 32 + nt * 8 + 2 * tig + jj;
                    if (n < N) {
                        float c = acc[mt][nt][half * 2 + jj];
                        if (EPI == 1) c += extra[n];
                        else if (EPI == 2 || EPI == 3) c = fmaxf(c + extra[ebase + n], 0.0f);
                        else if (EPI == 4) c += extra[ebase + n];
                        else if (EPI == 5) {
                            float x = c;
                            c = 0.5f * x * (1.0f + tanhf(0.7978845608028654f *
                                                         (x + 0.044715f * x * x * x)));
                        }
                        C[(size_t)r * N + n] = c;
                    }
                }
            }
        }
    }
}

// ---------------- attention (B=2048 edges, S=8, NH=4, HD=64) ----------------
__global__ void __launch_bounds__(256) attention_kernel() {
    __shared__ float qs[8][DG], ks[8][DG], vs[8][DG];
    int b = blockIdx.x;
    int tid = threadIdx.x;
    for (int i = tid; i < 8 * DG; i += 256) {
        int s = i >> 8, c = i & 255;
        size_t off = (size_t)(b * 8 + s) * DG + c;
        qs[s][c] = g_q[off];
        ks[s][c] = g_k[off];
        vs[s][c] = g_v[off];
    }
    __syncthreads();

    int h  = tid >> 6;
    int qx = (tid >> 3) & 7;
    int kx = tid & 7;
    float att = 0.0f;
    #pragma unroll
    for (int d = 0; d < HD; d++)
        att += qs[qx][h * HD + d] * ks[kx][h * HD + d];
    att *= 0.125f;

    float mx = att;
    mx = fmaxf(mx, __shfl_xor_sync(0xffffffffu, mx, 4));
    mx = fmaxf(mx, __shfl_xor_sync(0xffffffffu, mx, 2));
    mx = fmaxf(mx, __shfl_xor_sync(0xffffffffu, mx, 1));
    float ex = expf(att - mx);
    float sm = ex;
    sm += __shfl_xor_sync(0xffffffffu, sm, 4);
    sm += __shfl_xor_sync(0xffffffffu, sm, 2);
    sm += __shfl_xor_sync(0xffffffffu, sm, 1);
    float a = ex / sm;

    int lane = tid & 31;
    int base = lane & ~7;
    float a_all[8];
    #pragma unroll
    for (int kk = 0; kk < 8; kk++)
        a_all[kk] = __shfl_sync(0xffffffffu, a, base + kk);

    #pragma unroll
    for (int t2 = 0; t2 < 8; t2++) {
        int d = kx * 8 + t2;
        float o = 0.0f;
        #pragma unroll
        for (int kk = 0; kk < 8; kk++)
            o += a_all[kk] * vs[kk][h * HD + d];
        g_ao[(size_t)(b * 8 + qx) * DG + h * HD + d] = o;
    }
}

// ---------------- LM-head softmax ----------------
__global__ void row_softmax_stats(const float* __restrict__ logits) {
    int row = blockIdx.x;
    const float* p = logits + (size_t)row * VOCAB;
    __shared__ float sm[256];
    float m = -1e30f;
    for (int i = threadIdx.x; i < VOCAB; i += 256) m = fmaxf(m, p[i]);
    sm[threadIdx.x] = m; __syncthreads();
    for (int s = 128; s > 0; s >>= 1) {
        if (threadIdx.x < s) sm[threadIdx.x] = fmaxf(sm[threadIdx.x], sm[threadIdx.x + s]);
        __syncthreads();
    }
    float M = sm[0]; __syncthreads();
    float ssum = 0.0f;
    for (int i = threadIdx.x; i < VOCAB; i += 256) ssum += expf(p[i] - M);
    sm[threadIdx.x] = ssum; __syncthreads();
    for (int s = 128; s > 0; s >>= 1) {
        if (threadIdx.x < s) sm[threadIdx.x] += sm[threadIdx.x + s];
        __syncthreads();
    }
    if (threadIdx.x == 0) { g_rmax[row] = M; g_rinv[row] = 1.0f / sm[0]; }
}

__global__ void softmax_normalize(float* __restrict__ probs) {
    int col = blockIdx.x * 256 + threadIdx.x;
    int row = blockIdx.y;
    if (col >= VOCAB) return;
    size_t idx = (size_t)row * VOCAB + col;
    probs[idx] = expf(probs[idx] - g_rmax[row]) * g_rinv[row];
}

// ---------------- host launcher ----------------
static void launch_gemm(int epi, const float* A, const float* B, float* C,
                        int M, int N, int K,
                        const float* extra = nullptr, const int* gidx = nullptr, int ldex = 0) {
    dim3 grid((N + TBN - 1) / TBN, M / TBM), blk(256);
    switch (epi) {
        case 0: tmma_k<0><<<grid, blk>>>(A, B, C, M, N, K, extra, gidx, ldex); break;
        case 1: tmma_k<1><<<grid, blk>>>(A, B, C, M, N, K, extra, gidx, ldex); break;
        case 2: tmma_k<2><<<grid, blk>>>(A, B, C, M, N, K, extra, gidx, ldex); break;
        case 3: tmma_k<3><<<grid, blk>>>(A, B, C, M, N, K, extra, gidx, ldex); break;
        case 4: tmma_k<4><<<grid, blk>>>(A, B, C, M, N, K, extra, gidx, ldex); break;
        case 5: tmma_k<5><<<grid, blk>>>(A, B, C, M, N, K, extra, gidx, ldex); break;
    }
}

template <typename T>
static T* sym_addr(const void* sym) {
    void* p = nullptr;
    cudaGetSymbolAddress(&p, sym);
    return (T*)p;
}

extern "C" void kernel_launch(void* const* d_in, const int* in_sizes, int n_in,
                              void* d_out, int out_size) {
    const int*   node_tokens = (const int*)d_in[0];
    const int*   edge_tokens = (const int*)d_in[1];
    const int*   edge_index  = (const int*)d_in[2];
    const void*  mask_rows   = d_in[3];
    const float* emb    = (const float*)d_in[4];
    const float* W_msg  = (const float*)d_in[5];
    const float* W_node = (const float*)d_in[6];
    const float* lc1_w  = (const float*)d_in[7];
    const float* lc1_b  = (const float*)d_in[8];
    const float* lc2_w  = (const float*)d_in[9];
    const float* lc2_b  = (const float*)d_in[10];
    const float* Wq  = (const float*)d_in[11];
    const float* Wk  = (const float*)d_in[12];
    const float* Wv  = (const float*)d_in[13];
    const float* Wo  = (const float*)d_in[14];
    const float* Wf1 = (const float*)d_in[15];
    const float* Wf2 = (const float*)d_in[16];

    float* out = (float*)d_out;
    bool concat = (out_size != ROWS * VOCAB);
    float* labels_out = concat ? out : nullptr;
    float* probs      = concat ? out + ROWS : out;

    const int* src = edge_index;
    const int* dst = edge_index + N_EDGES;

    float* px   = sym_addr<float>(g_x);
    float* pe   = sym_addr<float>(g_e);
    float* pmsg = sym_addr<float>(g_msg);
    float* pagg = sym_addr<float>(g_agg);
    float* ph   = sym_addr<float>(g_h);
    float* peh  = sym_addr<float>(g_eh);
    float* pzg  = sym_addr<float>(g_zg);
    float* pq   = sym_addr<float>(g_q);
    float* pk   = sym_addr<float>(g_k);
    float* pv   = sym_addr<float>(g_v);
    float* pao  = sym_addr<float>(g_ao);
    float* px1  = sym_addr<float>(g_x1);
    float* pffn = sym_addr<float>(g_ffn);
    float* px2  = sym_addr<float>(g_x2);
    float* py   = sym_addr<float>(g_y);
    float* pembT= sym_addr<float>(g_embT);
    int*   pmt  = sym_addr<int>(g_mtok);

    // 1. mask dtype detect + labels/masked tokens
    detect_mask_kernel<<<1, 512>>>((const int*)mask_rows);
    mask_kernel<<<(N_EDGES * L_TOK + 255) / 256, 256>>>(edge_tokens, mask_rows, labels_out);

    // 2. embeddings
    embed_kernel<<<(N_NODES * FD + 255) / 256, 256>>>(node_tokens, emb, px, N_NODES * FD);
    embed_kernel<<<(N_EDGES * FD + 255) / 256, 256>>>(pmt, emb, pe, N_EDGES * FD);
    transpose_emb_kernel<<<(D_GNN * VOCAB + 255) / 256, 256>>>(emb);

    // 3. GNN
    launch_gemm(3, pe, W_msg, pmsg, N_EDGES, FD, FD, px, src, FD);
    zero_kernel<<<(N_NODES * FD + 255) / 256, 256>>>(pagg, N_NODES * FD);
    scatter_add_kernel<<<(N_EDGES * FD + 255) / 256, 256>>>(dst);
    launch_gemm(2, px, W_node, ph, N_NODES, FD, FD, pagg, nullptr, FD);
    edge_gather_kernel<<<(N_EDGES * FD + 255) / 256, 256>>>(src, dst);

    // 4. lc1
    launch_gemm(1, peh, lc1_w, pzg, ROWS, DG, D_GNN, lc1_b);

    // 5. transformer
    launch_gemm(0, pzg, Wq, pq, ROWS, DG, DG);
    launch_gemm(0, pzg, Wk, pk, ROWS, DG, DG);
    launch_gemm(0, pzg, Wv, pv, ROWS, DG, DG);
    attention_kernel<<<N_EDGES, 256>>>();
    launch_gemm(4, pao, Wo, px1, ROWS, DG, DG, pzg, nullptr, DG);
    launch_gemm(5, px1, Wf1, pffn, ROWS, 4 * DG, DG);
    launch_gemm(4, pffn, Wf2, px2, ROWS, DG, 4 * DG, px1, nullptr, DG);

    // 6. lc2 + LM head + softmax
    launch_gemm(1, px2, lc2_w, py, ROWS, D_GNN, DG, lc2_b);
    launch_gemm(0, py, pembT, probs, ROWS, VOCAB, D_GNN);
    row_softmax_stats<<<ROWS, 256>>>(probs);
    dim3 ngrid((VOCAB + 255) / 256, ROWS);
    softmax_normalize<<<ngrid, 256>>>(probs);
}

// round 3
// speedup vs baseline: 3.6059x; 2.0092x over previous
#include <cuda_runtime.h>
#include <cuda_bf16.h>
#include <math.h>
#include <stdint.h>

// ---------------- problem constants ----------------
#define VOCAB   10000
#define D_GNN   64
#define L_TOK   8
#define DG      256
#define NH      4
#define HD      64
#define N_NODES 8192
#define N_EDGES 2048
#define FD      512
#define ROWS    16384
#define NTMAX   80          // max vocab tiles (ceil(10000/128)=79)

// ---------------- scratch (static device memory) ----------------
__device__ float g_x   [N_NODES * FD];
__device__ float g_e   [N_EDGES * FD];
__device__ float g_msg [N_EDGES * FD];
__device__ float g_agg [N_NODES * FD];
__device__ float g_h   [N_NODES * FD];
__device__ float g_eh  [N_EDGES * FD];
__device__ float g_zg  [ROWS * DG];
__device__ float g_qkv [ROWS * 3 * DG];      // packed q|k|v per row
__device__ float g_wqkv[DG * 3 * DG];        // packed [256,768]
__device__ float g_ao  [ROWS * DG];
__device__ float g_x1  [ROWS * DG];
__device__ float g_ffn [ROWS * 4 * DG];
__device__ float g_x2  [ROWS * DG];
__device__ float g_y   [ROWS * D_GNN];
__device__ float g_embT[D_GNN * VOCAB];
__device__ int   g_mtok[N_EDGES * L_TOK];
__device__ float2 g_tstat[ROWS * NTMAX];     // per-(row,tile) (max, sumexp)
__device__ float g_rmax[ROWS];
__device__ float g_rinv[ROWS];
__device__ int   g_mask_mode;

// ---------------- mask dtype detection ----------------
__global__ void detect_mask_kernel(const int* __restrict__ mr) {
    __shared__ int notint, notflt;
    if (threadIdx.x == 0) { notint = 0; notflt = 0; }
    __syncthreads();
    int w = mr[threadIdx.x];
    if (w != 0 && w != 1)          atomicExch(&notint, 1);
    if (w != 0 && w != 0x3F800000) atomicExch(&notflt, 1);
    __syncthreads();
    if (threadIdx.x == 0)
        g_mask_mode = notint ? (notflt ? 2 : 1) : 0;
}

__global__ void mask_kernel(const int* __restrict__ etok, const void* __restrict__ maskraw,
                            float* labels_out) {
    int i = blockIdx.x * blockDim.x + threadIdx.x;
    if (i >= N_EDGES * L_TOK) return;
    int e = i >> 3;
    int t = etok[i];
    bool mr;
    int mode = g_mask_mode;
    if (mode == 0)      mr = ((const int*)maskraw)[e] != 0;
    else if (mode == 1) mr = ((const float*)maskraw)[e] != 0.0f;
    else                mr = ((const unsigned char*)maskraw)[e] != 0;
    bool msk = mr && (t >= 4);
    g_mtok[i] = msk ? 4 : t;
    if (labels_out) labels_out[i] = msk ? (float)t : -100.0f;
}

__global__ void embed_kernel(const int* __restrict__ tok, const float* __restrict__ emb,
                             float* __restrict__ out, int total) {
    int i = blockIdx.x * blockDim.x + threadIdx.x;
    if (i >= total) return;
    int ti = i >> 6;
    int d  = i & 63;
    out[i] = emb[tok[ti] * 64 + d];
}

__global__ void transpose_emb_kernel(const float* __restrict__ emb) {
    int i = blockIdx.x * blockDim.x + threadIdx.x;
    if (i >= D_GNN * VOCAB) return;
    int k = i / VOCAB, v = i - k * VOCAB;
    g_embT[i] = emb[v * 64 + k];
}

__global__ void pack_qkv_kernel(const float* __restrict__ Wq, const float* __restrict__ Wk,
                                const float* __restrict__ Wv) {
    int i = blockIdx.x * blockDim.x + threadIdx.x;
    if (i >= DG * DG) return;
    int k = i >> 8, n = i & 255;
    g_wqkv[k * 768 + n]       = Wq[i];
    g_wqkv[k * 768 + 256 + n] = Wk[i];
    g_wqkv[k * 768 + 512 + n] = Wv[i];
}

__global__ void zero_kernel(float* __restrict__ p, int n) {
    int i = blockIdx.x * blockDim.x + threadIdx.x;
    if (i < n) p[i] = 0.0f;
}

__global__ void scatter_add_kernel(const int* __restrict__ dst) {
    int i = blockIdx.x * blockDim.x + threadIdx.x;
    if (i >= N_EDGES * FD) return;
    int e = i >> 9, c = i & 511;
    atomicAdd(&g_agg[dst[e] * FD + c], g_msg[i]);
}

__global__ void edge_gather_kernel(const int* __restrict__ src, const int* __restrict__ dst) {
    int i = blockIdx.x * blockDim.x + threadIdx.x;
    if (i >= N_EDGES * FD) return;
    int e = i >> 9, c = i & 511;
    g_eh[i] = g_h[src[e] * FD + c] + g_h[dst[e] * FD + c];
}

// ---------------- tf32 tensor-core GEMM, cp.async double buffered ----------------
// EPI: 0 plain | 1 +bias[n] | 2 relu(+extra[m*ld+n]) | 3 relu(+extra[gidx[m]*ld+n])
//      4 +extra[m*ld+n] | 5 gelu | 6 plain + fused softmax tile stats

__device__ __forceinline__ void mma_tf32(float c[4], const uint32_t a[4], const uint32_t b[2]) {
    asm volatile(
        "mma.sync.aligned.m16n8k8.row.col.f32.tf32.tf32.f32 "
        "{%0,%1,%2,%3}, {%4,%5,%6,%7}, {%8,%9}, {%0,%1,%2,%3};"
        : "+f"(c[0]), "+f"(c[1]), "+f"(c[2]), "+f"(c[3])
        : "r"(a[0]), "r"(a[1]), "r"(a[2]), "r"(a[3]), "r"(b[0]), "r"(b[1]));
}

__device__ __forceinline__ void cp_async16(uint32_t dst, const void* src, bool pred) {
    int sz = pred ? 16 : 0;
    asm volatile("cp.async.cg.shared.global [%0], [%1], 16, %2;\n"
                 :: "r"(dst), "l"(src), "r"(sz));
}
__device__ __forceinline__ void cp_commit() {
    asm volatile("cp.async.commit_group;\n");
}
__device__ __forceinline__ void cp_wait1() {
    asm volatile("cp.async.wait_group 1;\n");
}

#define TBM 128
#define TBN 128
#define TBK 16
#define ASTR 20     // As row stride (floats); bank map (20*rm + tig) -> conflict-free
#define BSTR 136    // Bs row stride; bank map (8*tig + g) -> conflict-free

template<int EPI>
__global__ void __launch_bounds__(256)
tmma_k(const float* __restrict__ A, const float* __restrict__ B, float* __restrict__ C,
       int M, int N, int K,
       const float* __restrict__ extra, const int* __restrict__ gidx, int ldex,
       float2* __restrict__ tstat) {
    __shared__ float As[2][TBM][ASTR];
    __shared__ float Bs[2][TBK][BSTR];
    __shared__ float2 sstat[TBM][4];

    int tid  = threadIdx.x;
    int lane = tid & 31;
    int warp = tid >> 5;
    int wm = warp & 1;
    int wn = warp >> 1;
    int g   = lane >> 2;
    int tig = lane & 3;
    int m0 = blockIdx.y * TBM;
    int n0 = blockIdx.x * TBN;

    float acc[4][4][4] = {};

    // per-thread load slots
    int am[2], aq[2], bk[2], bn[2];
    #pragma unroll
    for (int i = 0; i < 2; i++) {
        int slot = tid + i * 256;
        am[i] = slot >> 2;           // 0..127
        aq[i] = (slot & 3) << 2;     // 0,4,8,12
        bk[i] = slot >> 5;           // 0..15
        bn[i] = (slot & 31) << 2;    // 0..124
    }

    auto issue_load = [&](int s, int k0) {
        #pragma unroll
        for (int i = 0; i < 2; i++) {
            uint32_t da = (uint32_t)__cvta_generic_to_shared(&As[s][am[i]][aq[i]]);
            cp_async16(da, A + (size_t)(m0 + am[i]) * K + k0 + aq[i], true);
            int gn = n0 + bn[i];
            uint32_t db = (uint32_t)__cvta_generic_to_shared(&Bs[s][bk[i]][bn[i]]);
            cp_async16(db, B + (size_t)(k0 + bk[i]) * N + gn, gn < N);
        }
    };

    int niter = K / TBK;
    issue_load(0, 0);
    cp_commit();

    for (int it = 0; it < niter; it++) {
        if (it + 1 < niter) issue_load((it + 1) & 1, (it + 1) * TBK);
        cp_commit();
        cp_wait1();
        __syncthreads();

        int s = it & 1;
        #pragma unroll
        for (int ks = 0; ks < TBK; ks += 8) {
            uint32_t af[4][4], bf[4][2];
            #pragma unroll
            for (int mt = 0; mt < 4; mt++) {
                int rm = wm * 64 + mt * 16 + g;
                af[mt][0] = __float_as_uint(As[s][rm    ][ks + tig    ]);
                af[mt][1] = __float_as_uint(As[s][rm + 8][ks + tig    ]);
                af[mt][2] = __float_as_uint(As[s][rm    ][ks + tig + 4]);
                af[mt][3] = __float_as_uint(As[s][rm + 8][ks + tig + 4]);
            }
            #pragma unroll
            for (int nt = 0; nt < 4; nt++) {
                int cn = wn * 32 + nt * 8 + g;
                bf[nt][0] = __float_as_uint(Bs[s][ks + tig    ][cn]);
                bf[nt][1] = __float_as_uint(Bs[s][ks + tig + 4][cn]);
            }
            #pragma unroll
            for (int mt = 0; mt < 4; mt++)
                #pragma unroll
                for (int nt = 0; nt < 4; nt++)
                    mma_tf32(acc[mt][nt], af[mt], bf[nt]);
        }
        __syncthreads();
    }

    // ---------------- epilogue ----------------
    #pragma unroll
    for (int mt = 0; mt < 4; mt++) {
        #pragma unroll
        for (int half = 0; half < 2; half++) {
            int rib = wm * 64 + mt * 16 + half * 8 + g;      // row in block
            int r = m0 + rib;
            int ebase = 0;
            if (EPI == 2 || EPI == 4) ebase = r * ldex;
            if (EPI == 3)             ebase = gidx[r] * ldex;

            float vals[8];
            #pragma unroll
            for (int nt = 0; nt < 4; nt++) {
                int n = n0 + wn * 32 + nt * 8 + 2 * tig;
                float c0 = acc[mt][nt][half * 2 + 0];
                float c1 = acc[mt][nt][half * 2 + 1];
                if (EPI == 1) { c0 += extra[n]; c1 += extra[n + 1]; }
                else if (EPI == 2 || EPI == 3) {
                    c0 = fmaxf(c0 + extra[ebase + n],     0.0f);
                    c1 = fmaxf(c1 + extra[ebase + n + 1], 0.0f);
                } else if (EPI == 4) {
                    c0 += extra[ebase + n]; c1 += extra[ebase + n + 1];
                } else if (EPI == 5) {
                    float x = c0;
                    c0 = 0.5f * x * (1.0f + tanhf(0.7978845608028654f * (x + 0.044715f * x * x * x)));
                    x = c1;
                    c1 = 0.5f * x * (1.0f + tanhf(0.7978845608028654f * (x + 0.044715f * x * x * x)));
                }
                vals[nt * 2 + 0] = c0;
                vals[nt * 2 + 1] = c1;
                if (n + 1 < N) {
                    *(float2*)&C[(size_t)r * N + n] = make_float2(c0, c1);
                } else if (n < N) {
                    C[(size_t)r * N + n] = c0;
                }
            }

            if (EPI == 6) {
                float rmx = -1e30f;
                #pragma unroll
                for (int j = 0; j < 8; j++) {
                    int n = n0 + wn * 32 + (j >> 1) * 8 + 2 * tig + (j & 1);
                    float v = (n < N) ? vals[j] : -1e30f;
                    vals[j] = v;
                    rmx = fmaxf(rmx, v);
                }
                float rsm = 0.0f;
                #pragma unroll
                for (int j = 0; j < 8; j++) rsm += __expf(vals[j] - rmx);
                // reduce across tig (lanes xor 1, 2)
                #pragma unroll
                for (int off = 1; off <= 2; off <<= 1) {
                    float om = __shfl_xor_sync(0xffffffffu, rmx, off);
                    float os = __shfl_xor_sync(0xffffffffu, rsm, off);
                    float nm = fmaxf(rmx, om);
                    rsm = rsm * __expf(rmx - nm) + os * __expf(om - nm);
                    rmx = nm;
                }
                if (tig == 0) sstat[rib][wn] = make_float2(rmx, rsm);
            }
        }
    }

    if (EPI == 6) {
        __syncthreads();
        if (tid < TBM) {
            float m = -1e30f, ssum = 0.0f;
            #pragma unroll
            for (int w = 0; w < 4; w++) {
                float2 p = sstat[tid][w];
                float nm = fmaxf(m, p.x);
                ssum = ssum * __expf(m - nm) + p.y * __expf(p.x - nm);
                m = nm;
            }
            tstat[(size_t)(m0 + tid) * gridDim.x + blockIdx.x] = make_float2(m, ssum);
        }
    }
}

// ---------------- softmax combine + normalize ----------------
__global__ void combine_stats_kernel(int ntile) {
    int row = blockIdx.x * blockDim.x + threadIdx.x;
    if (row >= ROWS) return;
    float m = -1e30f, s = 0.0f;
    for (int t = 0; t < ntile; t++) {
        float2 p = g_tstat[(size_t)row * ntile + t];
        float nm = fmaxf(m, p.x);
        s = s * __expf(m - nm) + p.y * __expf(p.x - nm);
        m = nm;
    }
    g_rmax[row] = m;
    g_rinv[row] = 1.0f / s;
}

__global__ void normalize_kernel(float* __restrict__ probs) {
    int idx = blockIdx.x * blockDim.x + threadIdx.x;    // float4 index
    const int PER_ROW = VOCAB / 4;                      // 2500
    if (idx >= ROWS * PER_ROW) return;
    int row = idx / PER_ROW;
    int c4  = idx - row * PER_ROW;
    float m = g_rmax[row], inv = g_rinv[row];
    size_t off = (size_t)row * VOCAB + c4 * 4;
    float4 v = *(const float4*)(probs + off);
    v.x = __expf(v.x - m) * inv;
    v.y = __expf(v.y - m) * inv;
    v.z = __expf(v.z - m) * inv;
    v.w = __expf(v.w - m) * inv;
    *(float4*)(probs + off) = v;
}

// ---------------- attention (packed qkv) ----------------
__global__ void __launch_bounds__(256) attention_kernel() {
    __shared__ float qs[8][DG], ks[8][DG], vs[8][DG];
    int b = blockIdx.x;
    int tid = threadIdx.x;
    for (int i = tid; i < 8 * DG; i += 256) {
        int s = i >> 8, c = i & 255;
        size_t off = (size_t)(b * 8 + s) * 768 + c;
        qs[s][c] = g_qkv[off];
        ks[s][c] = g_qkv[off + 256];
        vs[s][c] = g_qkv[off + 512];
    }
    __syncthreads();

    int h  = tid >> 6;
    int qx = (tid >> 3) & 7;
    int kx = tid & 7;
    float att = 0.0f;
    #pragma unroll
    for (int d = 0; d < HD; d++)
        att += qs[qx][h * HD + d] * ks[kx][h * HD + d];
    att *= 0.125f;

    float mx = att;
    mx = fmaxf(mx, __shfl_xor_sync(0xffffffffu, mx, 4));
    mx = fmaxf(mx, __shfl_xor_sync(0xffffffffu, mx, 2));
    mx = fmaxf(mx, __shfl_xor_sync(0xffffffffu, mx, 1));
    float ex = expf(att - mx);
    float sm = ex;
    sm += __shfl_xor_sync(0xffffffffu, sm, 4);
    sm += __shfl_xor_sync(0xffffffffu, sm, 2);
    sm += __shfl_xor_sync(0xffffffffu, sm, 1);
    float a = ex / sm;

    int lane = tid & 31;
    int base = lane & ~7;
    float a_all[8];
    #pragma unroll
    for (int kk = 0; kk < 8; kk++)
        a_all[kk] = __shfl_sync(0xffffffffu, a, base + kk);

    #pragma unroll
    for (int t2 = 0; t2 < 8; t2++) {
        int d = kx * 8 + t2;
        float o = 0.0f;
        #pragma unroll
        for (int kk = 0; kk < 8; kk++)
            o += a_all[kk] * vs[kk][h * HD + d];
        g_ao[(size_t)(b * 8 + qx) * DG + h * HD + d] = o;
    }
}

// ---------------- host launcher ----------------
static void launch_gemm(int epi, const float* A, const float* B, float* C,
                        int M, int N, int K,
                        const float* extra = nullptr, const int* gidx = nullptr, int ldex = 0,
                        float2* tstat = nullptr) {
    dim3 grid((N + TBN - 1) / TBN, M / TBM), blk(256);
    switch (epi) {
        case 0: tmma_k<0><<<grid, blk>>>(A, B, C, M, N, K, extra, gidx, ldex, tstat); break;
        case 1: tmma_k<1><<<grid, blk>>>(A, B, C, M, N, K, extra, gidx, ldex, tstat); break;
        case 2: tmma_k<2><<<grid, blk>>>(A, B, C, M, N, K, extra, gidx, ldex, tstat); break;
        case 3: tmma_k<3><<<grid, blk>>>(A, B, C, M, N, K, extra, gidx, ldex, tstat); break;
        case 4: tmma_k<4><<<grid, blk>>>(A, B, C, M, N, K, extra, gidx, ldex, tstat); break;
        case 5: tmma_k<5><<<grid, blk>>>(A, B, C, M, N, K, extra, gidx, ldex, tstat); break;
        case 6: tmma_k<6><<<grid, blk>>>(A, B, C, M, N, K, extra, gidx, ldex, tstat); break;
    }
}

template <typename T>
static T* sym_addr(const void* sym) {
    void* p = nullptr;
    cudaGetSymbolAddress(&p, sym);
    return (T*)p;
}

extern "C" void kernel_launch(void* const* d_in, const int* in_sizes, int n_in,
                              void* d_out, int out_size) {
    const int*   node_tokens = (const int*)d_in[0];
    const int*   edge_tokens = (const int*)d_in[1];
    const int*   edge_index  = (const int*)d_in[2];
    const void*  mask_rows   = d_in[3];
    const float* emb    = (const float*)d_in[4];
    const float* W_msg  = (const float*)d_in[5];
    const float* W_node = (const float*)d_in[6];
    const float* lc1_w  = (const float*)d_in[7];
    const float* lc1_b  = (const float*)d_in[8];
    const float* lc2_w  = (const float*)d_in[9];
    const float* lc2_b  = (const float*)d_in[10];
    const float* Wq  = (const float*)d_in[11];
    const float* Wk  = (const float*)d_in[12];
    const float* Wv  = (const float*)d_in[13];
    const float* Wo  = (const float*)d_in[14];
    const float* Wf1 = (const float*)d_in[15];
    const float* Wf2 = (const float*)d_in[16];

    float* out = (float*)d_out;
    bool concat = (out_size != ROWS * VOCAB);
    float* labels_out = concat ? out : nullptr;
    float* probs      = concat ? out + ROWS : out;

    const int* src = edge_index;
    const int* dst = edge_index + N_EDGES;

    float* px   = sym_addr<float>(g_x);
    float* pe   = sym_addr<float>(g_e);
    float* pmsg = sym_addr<float>(g_msg);
    float* pagg = sym_addr<float>(g_agg);
    float* ph   = sym_addr<float>(g_h);
    float* peh  = sym_addr<float>(g_eh);
    float* pzg  = sym_addr<float>(g_zg);
    float* pqkv = sym_addr<float>(g_qkv);
    float* pwqkv= sym_addr<float>(g_wqkv);
    float* pao  = sym_addr<float>(g_ao);
    float* px1  = sym_addr<float>(g_x1);
    float* pffn = sym_addr<float>(g_ffn);
    float* px2  = sym_addr<float>(g_x2);
    float* py   = sym_addr<float>(g_y);
    float* pembT= sym_addr<float>(g_embT);
    int*   pmt  = sym_addr<int>(g_mtok);
    float2* pst = sym_addr<float2>(g_tstat);

    // 1. mask dtype detect + labels/masked tokens
    detect_mask_kernel<<<1, 512>>>((const int*)mask_rows);
    mask_kernel<<<(N_EDGES * L_TOK + 255) / 256, 256>>>(edge_tokens, mask_rows, labels_out);

    // 2. embeddings + weight packing
    embed_kernel<<<(N_NODES * FD + 255) / 256, 256>>>(node_tokens, emb, px, N_NODES * FD);
    embed_kernel<<<(N_EDGES * FD + 255) / 256, 256>>>(pmt, emb, pe, N_EDGES * FD);
    transpose_emb_kernel<<<(D_GNN * VOCAB + 255) / 256, 256>>>(emb);
    pack_qkv_kernel<<<(DG * DG + 255) / 256, 256>>>(Wq, Wk, Wv);

    // 3. GNN
    launch_gemm(3, pe, W_msg, pmsg, N_EDGES, FD, FD, px, src, FD);
    zero_kernel<<<(N_NODES * FD + 255) / 256, 256>>>(pagg, N_NODES * FD);
    scatter_add_kernel<<<(N_EDGES * FD + 255) / 256, 256>>>(dst);
    launch_gemm(2, px, W_node, ph, N_NODES, FD, FD, pagg, nullptr, FD);
    edge_gather_kernel<<<(N_EDGES * FD + 255) / 256, 256>>>(src, dst);

    // 4. lc1
    launch_gemm(1, peh, lc1_w, pzg, ROWS, DG, D_GNN, lc1_b);

    // 5. transformer
    launch_gemm(0, pzg, pwqkv, pqkv, ROWS, 3 * DG, DG);
    attention_kernel<<<N_EDGES, 256>>>();
    launch_gemm(4, pao, Wo, px1, ROWS, DG, DG, pzg, nullptr, DG);
    launch_gemm(5, px1, Wf1, pffn, ROWS, 4 * DG, DG);
    launch_gemm(4, pffn, Wf2, px2, ROWS, DG, 4 * DG, px1, nullptr, DG);

    // 6. lc2 + LM head (with fused softmax stats) + softmax
    launch_gemm(1, px2, lc2_w, py, ROWS, D_GNN, DG, lc2_b);
    launch_gemm(6, py, pembT, probs, ROWS, VOCAB, D_GNN, nullptr, nullptr, 0, pst);
    int ntile = (VOCAB + TBN - 1) / TBN;
    combine_stats_kernel<<<(ROWS + 255) / 256, 256>>>(ntile);
    int tot4 = ROWS * (VOCAB / 4);
    normalize_kernel<<<(tot4 + 255) / 256, 256>>>(probs);
}

// round 4
// speedup vs baseline: 3.6660x; 1.0166x over previous
#include <cuda_runtime.h>
#include <cuda_bf16.h>
#include <math.h>
#include <stdint.h>

// ---------------- problem constants ----------------
#define VOCAB   10000
#define D_GNN   64
#define L_TOK   8
#define DG      256
#define NH      4
#define HD      64
#define N_NODES 8192
#define N_EDGES 2048
#define FD      512
#define ROWS    16384
#define NTMAX   80

// ---------------- scratch (static device memory) ----------------
__device__ float g_x   [N_NODES * FD];
__device__ float g_e   [N_EDGES * FD];
__device__ float g_msg [N_EDGES * FD];
__device__ float g_agg [N_NODES * FD];
__device__ float g_h   [N_NODES * FD];
__device__ float g_eh  [N_EDGES * FD];
__device__ float g_zg  [ROWS * DG];
__device__ float g_qkv [ROWS * 3 * DG];
__device__ float g_wqkv[DG * 3 * DG];
__device__ float g_ao  [ROWS * DG];
__device__ float g_x1  [ROWS * DG];
__device__ float g_ffn [ROWS * 4 * DG];
__device__ float g_x2  [ROWS * DG];
__device__ float g_y   [ROWS * D_GNN];
__device__ float g_embT[D_GNN * VOCAB];
__device__ int   g_mtok[N_EDGES * L_TOK];
__device__ float2 g_tstat[ROWS * NTMAX];
__device__ float g_rmax[ROWS];
__device__ float g_rinv[ROWS];
__device__ int   g_mask_mode;

// ---------------- mask dtype detection ----------------
__global__ void detect_mask_kernel(const int* __restrict__ mr) {
    __shared__ int notint, notflt;
    if (threadIdx.x == 0) { notint = 0; notflt = 0; }
    __syncthreads();
    int w = mr[threadIdx.x];
    if (w != 0 && w != 1)          atomicExch(&notint, 1);
    if (w != 0 && w != 0x3F800000) atomicExch(&notflt, 1);
    __syncthreads();
    if (threadIdx.x == 0)
        g_mask_mode = notint ? (notflt ? 2 : 1) : 0;
}

__global__ void mask_kernel(const int* __restrict__ etok, const void* __restrict__ maskraw,
                            float* labels_out) {
    int i = blockIdx.x * blockDim.x + threadIdx.x;
    if (i >= N_EDGES * L_TOK) return;
    int e = i >> 3;
    int t = etok[i];
    bool mr;
    int mode = g_mask_mode;
    if (mode == 0)      mr = ((const int*)maskraw)[e] != 0;
    else if (mode == 1) mr = ((const float*)maskraw)[e] != 0.0f;
    else                mr = ((const unsigned char*)maskraw)[e] != 0;
    bool msk = mr && (t >= 4);
    g_mtok[i] = msk ? 4 : t;
    if (labels_out) labels_out[i] = msk ? (float)t : -100.0f;
}

// float4 embedding gather: one thread per float4 (16 per row of 64)
__global__ void embed_kernel(const int* __restrict__ tok, const float* __restrict__ emb,
                             float4* __restrict__ out, int total4) {
    int i = blockIdx.x * blockDim.x + threadIdx.x;
    if (i >= total4) return;
    int ti = i >> 4;
    int d4 = i & 15;
    out[i] = *(const float4*)(emb + tok[ti] * 64 + d4 * 4);
}

__global__ void transpose_emb_kernel(const float* __restrict__ emb) {
    int i = blockIdx.x * blockDim.x + threadIdx.x;
    if (i >= D_GNN * VOCAB) return;
    int k = i / VOCAB, v = i - k * VOCAB;
    g_embT[i] = emb[v * 64 + k];
}

__global__ void pack_qkv_kernel(const float* __restrict__ Wq, const float* __restrict__ Wk,
                                const float* __restrict__ Wv) {
    int i = blockIdx.x * blockDim.x + threadIdx.x;
    if (i >= DG * DG) return;
    int k = i >> 8, n = i & 255;
    g_wqkv[k * 768 + n]       = Wq[i];
    g_wqkv[k * 768 + 256 + n] = Wk[i];
    g_wqkv[k * 768 + 512 + n] = Wv[i];
}

__global__ void zero_kernel(float4* __restrict__ p, int n4) {
    int i = blockIdx.x * blockDim.x + threadIdx.x;
    if (i < n4) p[i] = make_float4(0.f, 0.f, 0.f, 0.f);
}

__global__ void scatter_add_kernel(const int* __restrict__ dst) {
    int i = blockIdx.x * blockDim.x + threadIdx.x;      // float4 index
    if (i >= N_EDGES * FD / 4) return;
    int e = i >> 7, c4 = i & 127;
    float4 v = *(const float4*)(g_msg + ((size_t)e << 9) + c4 * 4);
    float* base = g_agg + (size_t)dst[e] * FD + c4 * 4;
    atomicAdd(base + 0, v.x);
    atomicAdd(base + 1, v.y);
    atomicAdd(base + 2, v.z);
    atomicAdd(base + 3, v.w);
}

__global__ void edge_gather_kernel(const int* __restrict__ src, const int* __restrict__ dst) {
    int i = blockIdx.x * blockDim.x + threadIdx.x;      // float4 index
    if (i >= N_EDGES * FD / 4) return;
    int e = i >> 7, c4 = i & 127;
    const float4* s = (const float4*)(g_h + (size_t)src[e] * FD) + c4;
    const float4* d = (const float4*)(g_h + (size_t)dst[e] * FD) + c4;
    float4 a = *s, b = *d;
    a.x += b.x; a.y += b.y; a.z += b.z; a.w += b.w;
    *((float4*)(g_eh + ((size_t)e << 9)) + c4) = a;
}

// ---------------- tf32 tensor-core GEMM, cp.async double buffered ----------------
// EPI: 0 plain | 1 +bias[n] | 2 relu(+extra[m*ld+n]) | 3 relu(+extra[gidx[m]*ld+n])
//      4 +extra[m*ld+n] | 5 gelu | 7 stats-only (no C write) | 8 softmax-write

__device__ __forceinline__ void mma_tf32(float c[4], const uint32_t a[4], const uint32_t b[2]) {
    asm volatile(
        "mma.sync.aligned.m16n8k8.row.col.f32.tf32.tf32.f32 "
        "{%0,%1,%2,%3}, {%4,%5,%6,%7}, {%8,%9}, {%0,%1,%2,%3};"
        : "+f"(c[0]), "+f"(c[1]), "+f"(c[2]), "+f"(c[3])
        : "r"(a[0]), "r"(a[1]), "r"(a[2]), "r"(a[3]), "r"(b[0]), "r"(b[1]));
}

__device__ __forceinline__ void cp_async16(uint32_t dst, const void* src, bool pred) {
    int sz = pred ? 16 : 0;
    asm volatile("cp.async.cg.shared.global [%0], [%1], 16, %2;\n"
                 :: "r"(dst), "l"(src), "r"(sz));
}
__device__ __forceinline__ void cp_commit() {
    asm volatile("cp.async.commit_group;\n");
}
__device__ __forceinline__ void cp_wait0() {
    asm volatile("cp.async.wait_group 0;\n");
}

#define TBM 128
#define TBN 128
#define TBK 16
#define ASTR 20
#define BSTR 136

template<int EPI>
__global__ void __launch_bounds__(256)
tmma_k(const float* __restrict__ A, const float* __restrict__ B, float* __restrict__ C,
       int M, int N, int K,
       const float* __restrict__ extra, const int* __restrict__ gidx, int ldex,
       float2* __restrict__ tstat) {
    __shared__ float As[2][TBM][ASTR];
    __shared__ float Bs[2][TBK][BSTR];
    __shared__ float2 sstat[TBM][4];

    int tid  = threadIdx.x;
    int lane = tid & 31;
    int warp = tid >> 5;
    int wm = warp & 1;
    int wn = warp >> 1;
    int g   = lane >> 2;
    int tig = lane & 3;
    int m0 = blockIdx.y * TBM;
    int n0 = blockIdx.x * TBN;

    float acc[4][4][4] = {};

    int am[2], aq[2], bk[2], bn[2];
    #pragma unroll
    for (int i = 0; i < 2; i++) {
        int slot = tid + i * 256;
        am[i] = slot >> 2;
        aq[i] = (slot & 3) << 2;
        bk[i] = slot >> 5;
        bn[i] = (slot & 31) << 2;
    }

    auto issue_load = [&](int s, int k0) {
        #pragma unroll
        for (int i = 0; i < 2; i++) {
            uint32_t da = (uint32_t)__cvta_generic_to_shared(&As[s][am[i]][aq[i]]);
            cp_async16(da, A + (size_t)(m0 + am[i]) * K + k0 + aq[i], true);
            int gn = n0 + bn[i];
            uint32_t db = (uint32_t)__cvta_generic_to_shared(&Bs[s][bk[i]][bn[i]]);
            cp_async16(db, B + (size_t)(k0 + bk[i]) * N + gn, gn < N);
        }
    };

    int niter = K / TBK;
    issue_load(0, 0);
    cp_commit();

    for (int it = 0; it < niter; it++) {
        cp_wait0();
        __syncthreads();
        if (it + 1 < niter) { issue_load((it + 1) & 1, (it + 1) * TBK); cp_commit(); }

        int s = it & 1;
        #pragma unroll
        for (int ks = 0; ks < TBK; ks += 8) {
            uint32_t af[4][4], bf[4][2];
            #pragma unroll
            for (int mt = 0; mt < 4; mt++) {
                int rm = wm * 64 + mt * 16 + g;
                af[mt][0] = __float_as_uint(As[s][rm    ][ks + tig    ]);
                af[mt][1] = __float_as_uint(As[s][rm + 8][ks + tig    ]);
                af[mt][2] = __float_as_uint(As[s][rm    ][ks + tig + 4]);
                af[mt][3] = __float_as_uint(As[s][rm + 8][ks + tig + 4]);
            }
            #pragma unroll
            for (int nt = 0; nt < 4; nt++) {
                int cn = wn * 32 + nt * 8 + g;
                bf[nt][0] = __float_as_uint(Bs[s][ks + tig    ][cn]);
                bf[nt][1] = __float_as_uint(Bs[s][ks + tig + 4][cn]);
            }
            #pragma unroll
            for (int mt = 0; mt < 4; mt++)
                #pragma unroll
                for (int nt = 0; nt < 4; nt++)
                    mma_tf32(acc[mt][nt], af[mt], bf[nt]);
        }
    }

    // ---------------- epilogue ----------------
    #pragma unroll
    for (int mt = 0; mt < 4; mt++) {
        #pragma unroll
        for (int half = 0; half < 2; half++) {
            int rib = wm * 64 + mt * 16 + half * 8 + g;
            int r = m0 + rib;
            int ebase = 0;
            if (EPI == 2 || EPI == 4) ebase = r * ldex;
            if (EPI == 3)             ebase = gidx[r] * ldex;
            float rmaxv = 0.0f, rinvv = 0.0f;
            if (EPI == 8) { rmaxv = g_rmax[r]; rinvv = g_rinv[r]; }

            float vals[8];
            #pragma unroll
            for (int nt = 0; nt < 4; nt++) {
                int n = n0 + wn * 32 + nt * 8 + 2 * tig;
                float c0 = acc[mt][nt][half * 2 + 0];
                float c1 = acc[mt][nt][half * 2 + 1];
                if (EPI == 1) { c0 += extra[n]; c1 += extra[n + 1]; }
                else if (EPI == 2 || EPI == 3) {
                    c0 = fmaxf(c0 + extra[ebase + n],     0.0f);
                    c1 = fmaxf(c1 + extra[ebase + n + 1], 0.0f);
                } else if (EPI == 4) {
                    c0 += extra[ebase + n]; c1 += extra[ebase + n + 1];
                } else if (EPI == 5) {
                    float x = c0;
                    c0 = 0.5f * x * (1.0f + tanhf(0.7978845608028654f * (x + 0.044715f * x * x * x)));
                    x = c1;
                    c1 = 0.5f * x * (1.0f + tanhf(0.7978845608028654f * (x + 0.044715f * x * x * x)));
                }
                vals[nt * 2 + 0] = c0;
                vals[nt * 2 + 1] = c1;
                if (EPI == 8) {
                    if (n < N) {
                        float p0 = __expf(c0 - rmaxv) * rinvv;
                        float p1 = __expf(c1 - rmaxv) * rinvv;
                        *(float2*)&C[(size_t)r * N + n] = make_float2(p0, p1);
                    }
                } else if (EPI != 7) {
                    if (n + 1 < N) {
                        *(float2*)&C[(size_t)r * N + n] = make_float2(c0, c1);
                    } else if (n < N) {
                        C[(size_t)r * N + n] = c0;
                    }
                }
            }

            if (EPI == 7) {
                float rmx = -1e30f;
                #pragma unroll
                for (int j = 0; j < 8; j++) {
                    int n = n0 + wn * 32 + (j >> 1) * 8 + 2 * tig + (j & 1);
                    float v = (n < N) ? vals[j] : -1e30f;
                    vals[j] = v;
                    rmx = fmaxf(rmx, v);
                }
                float rsm = 0.0f;
                #pragma unroll
                for (int j = 0; j < 8; j++) rsm += __expf(vals[j] - rmx);
                #pragma unroll
                for (int off = 1; off <= 2; off <<= 1) {
                    float om = __shfl_xor_sync(0xffffffffu, rmx, off);
                    float os = __shfl_xor_sync(0xffffffffu, rsm, off);
                    float nm = fmaxf(rmx, om);
                    rsm = rsm * __expf(rmx - nm) + os * __expf(om - nm);
                    rmx = nm;
                }
                if (tig == 0) sstat[rib][wn] = make_float2(rmx, rsm);
            }
        }
    }

    if (EPI == 7) {
        __syncthreads();
        if (tid < TBM) {
            float m = -1e30f, ssum = 0.0f;
            #pragma unroll
            for (int w = 0; w < 4; w++) {
                float2 p = sstat[tid][w];
                float nm = fmaxf(m, p.x);
                ssum = ssum * __expf(m - nm) + p.y * __expf(p.x - nm);
                m = nm;
            }
            tstat[(size_t)(m0 + tid) * gridDim.x + blockIdx.x] = make_float2(m, ssum);
        }
    }
}

// ---------------- softmax stat combine ----------------
__global__ void combine_stats_kernel(int ntile) {
    int row = blockIdx.x * blockDim.x + threadIdx.x;
    if (row >= ROWS) return;
    float m = -1e30f, s = 0.0f;
    for (int t = 0; t < ntile; t++) {
        float2 p = g_tstat[(size_t)row * ntile + t];
        float nm = fmaxf(m, p.x);
        s = s * __expf(m - nm) + p.y * __expf(p.x - nm);
        m = nm;
    }
    g_rmax[row] = m;
    g_rinv[row] = 1.0f / s;
}

// ---------------- attention ----------------
__global__ void __launch_bounds__(256) attention_kernel() {
    __shared__ float qs[8][DG], ks[8][DG], vs[8][DG];
    int b = blockIdx.x;
    int tid = threadIdx.x;
    for (int i = tid; i < 8 * DG; i += 256) {
        int s = i >> 8, c = i & 255;
        size_t off = (size_t)(b * 8 + s) * 768 + c;
        qs[s][c] = g_qkv[off];
        ks[s][c] = g_qkv[off + 256];
        vs[s][c] = g_qkv[off + 512];
    }
    __syncthreads();

    int h  = tid >> 6;
    int qx = (tid >> 3) & 7;
    int kx = tid & 7;
    float att = 0.0f;
    #pragma unroll
    for (int d = 0; d < HD; d++)
        att += qs[qx][h * HD + d] * ks[kx][h * HD + d];
    att *= 0.125f;

    float mx = att;
    mx = fmaxf(mx, __shfl_xor_sync(0xffffffffu, mx, 4));
    mx = fmaxf(mx, __shfl_xor_sync(0xffffffffu, mx, 2));
    mx = fmaxf(mx, __shfl_xor_sync(0xffffffffu, mx, 1));
    float ex = expf(att - mx);
    float sm = ex;
    sm += __shfl_xor_sync(0xffffffffu, sm, 4);
    sm += __shfl_xor_sync(0xffffffffu, sm, 2);
    sm += __shfl_xor_sync(0xffffffffu, sm, 1);
    float a = ex / sm;

    int lane = tid & 31;
    int base = lane & ~7;
    float a_all[8];
    #pragma unroll
    for (int kk = 0; kk < 8; kk++)
        a_all[kk] = __shfl_sync(0xffffffffu, a, base + kk);

    #pragma unroll
    for (int t2 = 0; t2 < 8; t2++) {
        int d = kx * 8 + t2;
        float o = 0.0f;
        #pragma unroll
        for (int kk = 0; kk < 8; kk++)
            o += a_all[kk] * vs[kk][h * HD + d];
        g_ao[(size_t)(b * 8 + qx) * DG + h * HD + d] = o;
    }
}

// ---------------- host launcher ----------------
static void launch_gemm(int epi, const float* A, const float* B, float* C,
                        int M, int N, int K,
                        const float* extra = nullptr, const int* gidx = nullptr, int ldex = 0,
                        float2* tstat = nullptr) {
    dim3 grid((N + TBN - 1) / TBN, M / TBM), blk(256);
    switch (epi) {
        case 0: tmma_k<0><<<grid, blk>>>(A, B, C, M, N, K, extra, gidx, ldex, tstat); break;
        case 1: tmma_k<1><<<grid, blk>>>(A, B, C, M, N, K, extra, gidx, ldex, tstat); break;
        case 2: tmma_k<2><<<grid, blk>>>(A, B, C, M, N, K, extra, gidx, ldex, tstat); break;
        case 3: tmma_k<3><<<grid, blk>>>(A, B, C, M, N, K, extra, gidx, ldex, tstat); break;
        case 4: tmma_k<4><<<grid, blk>>>(A, B, C, M, N, K, extra, gidx, ldex, tstat); break;
        case 5: tmma_k<5><<<grid, blk>>>(A, B, C, M, N, K, extra, gidx, ldex, tstat); break;
        case 7: tmma_k<7><<<grid, blk>>>(A, B, C, M, N, K, extra, gidx, ldex, tstat); break;
        case 8: tmma_k<8><<<grid, blk>>>(A, B, C, M, N, K, extra, gidx, ldex, tstat); break;
    }
}

template <typename T>
static T* sym_addr(const void* sym) {
    void* p = nullptr;
    cudaGetSymbolAddress(&p, sym);
    return (T*)p;
}

extern "C" void kernel_launch(void* const* d_in, const int* in_sizes, int n_in,
                              void* d_out, int out_size) {
    const int*   node_tokens = (const int*)d_in[0];
    const int*   edge_tokens = (const int*)d_in[1];
    const int*   edge_index  = (const int*)d_in[2];
    const void*  mask_rows   = d_in[3];
    const float* emb    = (const float*)d_in[4];
    const float* W_msg  = (const float*)d_in[5];
    const float* W_node = (const float*)d_in[6];
    const float* lc1_w  = (const float*)d_in[7];
    const float* lc1_b  = (const float*)d_in[8];
    const float* lc2_w  = (const float*)d_in[9];
    const float* lc2_b  = (const float*)d_in[10];
    const float* Wq  = (const float*)d_in[11];
    const float* Wk  = (const float*)d_in[12];
    const float* Wv  = (const float*)d_in[13];
    const float* Wo  = (const float*)d_in[14];
    const float* Wf1 = (const float*)d_in[15];
    const float* Wf2 = (const float*)d_in[16];

    float* out = (float*)d_out;
    bool concat = (out_size != ROWS * VOCAB);
    float* labels_out = concat ? out : nullptr;
    float* probs      = concat ? out + ROWS : out;

    const int* src = edge_index;
    const int* dst = edge_index + N_EDGES;

    float* px   = sym_addr<float>(g_x);
    float* pe   = sym_addr<float>(g_e);
    float* pmsg = sym_addr<float>(g_msg);
    float* pagg = sym_addr<float>(g_agg);
    float* ph   = sym_addr<float>(g_h);
    float* peh  = sym_addr<float>(g_eh);
    float* pzg  = sym_addr<float>(g_zg);
    float* pqkv = sym_addr<float>(g_qkv);
    float* pwqkv= sym_addr<float>(g_wqkv);
    float* pao  = sym_addr<float>(g_ao);
    float* px1  = sym_addr<float>(g_x1);
    float* pffn = sym_addr<float>(g_ffn);
    float* px2  = sym_addr<float>(g_x2);
    float* py   = sym_addr<float>(g_y);
    float* pembT= sym_addr<float>(g_embT);
    int*   pmt  = sym_addr<int>(g_mtok);
    float2* pst = sym_addr<float2>(g_tstat);

    // 1. mask dtype detect + labels/masked tokens
    detect_mask_kernel<<<1, 512>>>((const int*)mask_rows);
    mask_kernel<<<(N_EDGES * L_TOK + 255) / 256, 256>>>(edge_tokens, mask_rows, labels_out);

    // 2. embeddings + weight packing
    embed_kernel<<<(N_NODES * FD / 4 + 255) / 256, 256>>>(node_tokens, emb, (float4*)px, N_NODES * FD / 4);
    embed_kernel<<<(N_EDGES * FD / 4 + 255) / 256, 256>>>(pmt, emb, (float4*)pe, N_EDGES * FD / 4);
    transpose_emb_kernel<<<(D_GNN * VOCAB + 255) / 256, 256>>>(emb);
    pack_qkv_kernel<<<(DG * DG + 255) / 256, 256>>>(Wq, Wk, Wv);

    // 3. GNN
    launch_gemm(3, pe, W_msg, pmsg, N_EDGES, FD, FD, px, src, FD);
    zero_kernel<<<(N_NODES * FD / 4 + 255) / 256, 256>>>((float4*)pagg, N_NODES * FD / 4);
    scatter_add_kernel<<<(N_EDGES * FD / 4 + 255) / 256, 256>>>(dst);
    launch_gemm(2, px, W_node, ph, N_NODES, FD, FD, pagg, nullptr, FD);
    edge_gather_kernel<<<(N_EDGES * FD / 4 + 255) / 256, 256>>>(src, dst);

    // 4. lc1
    launch_gemm(1, peh, lc1_w, pzg, ROWS, DG, D_GNN, lc1_b);

    // 5. transformer
    launch_gemm(0, pzg, pwqkv, pqkv, ROWS, 3 * DG, DG);
    attention_kernel<<<N_EDGES, 256>>>();
    launch_gemm(4, pao, Wo, px1, ROWS, DG, DG, pzg, nullptr, DG);
    launch_gemm(5, px1, Wf1, pffn, ROWS, 4 * DG, DG);
    launch_gemm(4, pffn, Wf2, px2, ROWS, DG, 4 * DG, px1, nullptr, DG);

    // 6. lc2 + two-pass LM head (stats, then softmax-write; no intermediate logits traffic)
    launch_gemm(1, px2, lc2_w, py, ROWS, D_GNN, DG, lc2_b);
    launch_gemm(7, py, pembT, probs, ROWS, VOCAB, D_GNN, nullptr, nullptr, 0, pst);
    int ntile = (VOCAB + TBN - 1) / TBN;
    combine_stats_kernel<<<(ROWS + 255) / 256, 256>>>(ntile);
    launch_gemm(8, py, pembT, probs, ROWS, VOCAB, D_GNN, nullptr, nullptr, 0, pst);
}